// round 10
// baseline (speedup 1.0000x reference)
#include <cuda_runtime.h>
#include <math.h>
#include <stdint.h>

#define T_   6400
#define Dm   512
#define Nn   2048
#define NBUCK 128
#define INV_N (1.0f / 2048.0f)

// offsets = [0, 2048, 3584, 4608, 6400]; lengths all multiples of 64.
__constant__ int c_off[5] = {0, 2048, 3584, 4608, 6400};

__device__ float g_xn[(size_t)T_ * Dm];
__device__ float g_uvqkr[(size_t)Dm * 1024];
__device__ float g_h[(size_t)T_ * 1024];
__device__ float g_attn[(size_t)T_ * 256];
__device__ float g_oin[(size_t)T_ * 256];

// ---- tf32 / mma / cp.async helpers ----------------------------------------
__device__ __forceinline__ float tf32r(float x) {
    float y; asm("cvt.rna.tf32.f32 %0, %1;" : "=f"(y) : "f"(x)); return y;
}
__device__ __forceinline__ float4 tf32r4(float4 v) {
    v.x = tf32r(v.x); v.y = tf32r(v.y); v.z = tf32r(v.z); v.w = tf32r(v.w);
    return v;
}
__device__ __forceinline__ float tanh_hw(float x) {
    float y; asm("tanh.approx.f32 %0, %1;" : "=f"(y) : "f"(x)); return y;
}
__device__ __forceinline__ void mma8(float* c, const float* a, const float* b) {
    asm volatile(
        "mma.sync.aligned.m16n8k8.row.col.f32.tf32.tf32.f32 "
        "{%0,%1,%2,%3},{%4,%5,%6,%7},{%8,%9},{%0,%1,%2,%3};"
        : "+f"(c[0]), "+f"(c[1]), "+f"(c[2]), "+f"(c[3])
        : "r"(__float_as_uint(a[0])), "r"(__float_as_uint(a[1])),
          "r"(__float_as_uint(a[2])), "r"(__float_as_uint(a[3])),
          "r"(__float_as_uint(b[0])), "r"(__float_as_uint(b[1])));
}
__device__ __forceinline__ void cpa16(void* dst, const void* src) {
    uint32_t d = (uint32_t)__cvta_generic_to_shared(dst);
    asm volatile("cp.async.cg.shared.global [%0], [%1], 16;" :: "r"(d), "l"(src));
}
__device__ __forceinline__ void cpa_commit() { asm volatile("cp.async.commit_group;"); }
__device__ __forceinline__ void cpa_wait0()  { asm volatile("cp.async.wait_group 0;"); }

// ---------------------------------------------------------------------------
// tf32 pre-round of uvqk
// ---------------------------------------------------------------------------
__global__ __launch_bounds__(256) void cvt_tf32_kernel(const float4* __restrict__ in,
                                                       float4* __restrict__ out) {
    int i = blockIdx.x * 256 + threadIdx.x;
    out[i] = tf32r4(in[i]);
}

// ---------------------------------------------------------------------------
// LayerNorm over D=512, warp-per-row, tf32-rounded output
// ---------------------------------------------------------------------------
__global__ __launch_bounds__(256) void ln_x_kernel(const float* __restrict__ x,
                                                   float* __restrict__ xn) {
    int row = blockIdx.x * 8 + (threadIdx.x >> 5);
    int lane = threadIdx.x & 31;
    const float* r = x + (size_t)row * Dm;
    float4 v[4];
    float s = 0.f, q = 0.f;
#pragma unroll
    for (int i = 0; i < 4; i++) {
        v[i] = *reinterpret_cast<const float4*>(&r[lane * 4 + i * 128]);
        s += v[i].x + v[i].y + v[i].z + v[i].w;
        q += v[i].x * v[i].x + v[i].y * v[i].y + v[i].z * v[i].z + v[i].w * v[i].w;
    }
#pragma unroll
    for (int o = 16; o > 0; o >>= 1) {
        s += __shfl_xor_sync(0xffffffffu, s, o);
        q += __shfl_xor_sync(0xffffffffu, q, o);
    }
    float m = s * (1.f / Dm);
    float rstd = rsqrtf(q * (1.f / Dm) - m * m + 1e-6f);
    float* ov = xn + (size_t)row * Dm;
#pragma unroll
    for (int i = 0; i < 4; i++) {
        float4 w;
        w.x = tf32r((v[i].x - m) * rstd); w.y = tf32r((v[i].y - m) * rstd);
        w.z = tf32r((v[i].z - m) * rstd); w.w = tf32r((v[i].w - m) * rstd);
        *reinterpret_cast<float4*>(&ov[lane * 4 + i * 128]) = w;
    }
}

// ---------------------------------------------------------------------------
// h = silu(xn @ uvqkr)  tf32 MMA, 128x64 tile, BK=32, cp.async double buffer.
// q/k sections (cols >= 512) stored with per-8-col interleave permutation.
// ---------------------------------------------------------------------------
#define G1_SMEM ((2 * (128 * 36 + 32 * 72)) * 4)

__global__ __launch_bounds__(256) void gemm_silu_kernel(const float* __restrict__ A,
                                                        const float* __restrict__ Bm,
                                                        float* __restrict__ C) {
    extern __shared__ float sm[];
    float* sA = sm;            // [2][128][36]
    float* sB = sm + 9216;     // [2][32][72]
    int bm = blockIdx.y * 128, bn = blockIdx.x * 64;
    int tid = threadIdx.x, lane = tid & 31, wid = tid >> 5;
    int g = lane >> 2, t = lane & 3;
    int wm = (wid >> 1) * 32, wn = (wid & 1) * 32;

    auto pf = [&](int k0, int buf) {
        float* dA = sA + buf * 4608;
        float* dB = sB + buf * 2304;
#pragma unroll
        for (int p = 0; p < 4; p++) {
            int idx = tid + p * 256;
            int row = idx >> 3, f4 = (idx & 7) << 2;
            cpa16(&dA[row * 36 + f4], &A[(size_t)(bm + row) * Dm + k0 + f4]);
        }
#pragma unroll
        for (int p = 0; p < 2; p++) {
            int idx = tid + p * 256;
            int row = idx >> 4, f4 = (idx & 15) << 2;
            cpa16(&dB[row * 72 + f4], &Bm[(size_t)(k0 + row) * 1024 + bn + f4]);
        }
        cpa_commit();
    };

    float acc[2][4][4] = {};
    pf(0, 0);
    for (int it = 0; it < 16; it++) {
        cpa_wait0();
        __syncthreads();
        if (it + 1 < 16) pf((it + 1) * 32, (it + 1) & 1);
        float* cA = sA + (it & 1) * 4608;
        float* cB = sB + (it & 1) * 2304;
#pragma unroll
        for (int kk = 0; kk < 32; kk += 8) {
            float a[2][4], bb[4][2];
#pragma unroll
            for (int i = 0; i < 2; i++) {
                int r = wm + 16 * i + g;
                a[i][0] = cA[r * 36 + kk + t];
                a[i][1] = cA[(r + 8) * 36 + kk + t];
                a[i][2] = cA[r * 36 + kk + t + 4];
                a[i][3] = cA[(r + 8) * 36 + kk + t + 4];
            }
#pragma unroll
            for (int j = 0; j < 4; j++) {
                bb[j][0] = cB[(kk + t) * 72 + wn + 8 * j + g];
                bb[j][1] = cB[(kk + t + 4) * 72 + wn + 8 * j + g];
            }
#pragma unroll
            for (int i = 0; i < 2; i++)
#pragma unroll
                for (int j = 0; j < 4; j++) mma8(acc[i][j], a[i], bb[j]);
        }
        __syncthreads();
    }
    bool perm = (bn >= 512);
    int p0 = (t < 2) ? 4 * t : 4 * t - 7;
#pragma unroll
    for (int i = 0; i < 2; i++) {
        int r = bm + wm + 16 * i + g;
#pragma unroll
        for (int j = 0; j < 4; j++) {
            float* s = acc[i][j];
            float e0 = tf32r(__fdividef(s[0], 1.f + __expf(-s[0])));
            float e1 = tf32r(__fdividef(s[1], 1.f + __expf(-s[1])));
            float e2 = tf32r(__fdividef(s[2], 1.f + __expf(-s[2])));
            float e3 = tf32r(__fdividef(s[3], 1.f + __expf(-s[3])));
            if (!perm) {
                int c = bn + wn + 8 * j + 2 * t;
                *reinterpret_cast<float2*>(&C[(size_t)r * 1024 + c]) = make_float2(e0, e1);
                *reinterpret_cast<float2*>(&C[(size_t)(r + 8) * 1024 + c]) = make_float2(e2, e3);
            } else {
                int cb = bn + wn + 8 * j;
                C[(size_t)r * 1024 + cb + p0] = e0;
                C[(size_t)r * 1024 + cb + p0 + 2] = e1;
                C[(size_t)(r + 8) * 1024 + cb + p0] = e2;
                C[(size_t)(r + 8) * 1024 + cb + p0 + 2] = e3;
            }
        }
    }
}

// ---------------------------------------------------------------------------
// Split-K jagged causal attention.
// Score phase: bucket via exponent-bit trick (no MUFU), silu via HW tanh (1 MUFU).
// ---------------------------------------------------------------------------
#define ATTN_SMEM (22892 * 4)

__global__ __launch_bounds__(256) void attn_kernel(const float* __restrict__ h,
                                                   const int* __restrict__ ts,
                                                   const float* __restrict__ ts_w,
                                                   float* __restrict__ attn) {
    // decode unit -> (b, tile, chunk); chunks(t) = (t>>3)+1, tiles descending
    int u = blockIdx.x;
    int b;
    if (u < 80) { b = 0; }
    else if (u < 128) { b = 1; u -= 80; }
    else if (u < 152) { b = 2; u -= 128; }
    else { b = 3; u -= 152; }
    int base = c_off[b];
    int Tb = (c_off[b + 1] - base) >> 6;
    int tile = 0, chunk = 0;
    for (int tt = Tb - 1; tt >= 0; --tt) {
        int c = (tt >> 3) + 1;
        if (u < c) { tile = tt; chunk = u; break; }
        u -= c;
    }
    int head = blockIdx.y;
    int q0 = tile * 64;
    int kt0 = chunk * 8;
    int nkt = min(kt0 + 8, tile + 1) - kt0;

    extern __shared__ float sm[];
    float* sQS = sm;                // [64][72]: Q during init, then S
    float* sKb = sm + 4608;         // [2][64][72]
    float* sVb = sm + 13824;        // [2][64][68] (rows permuted)
    float* sW  = sm + 22528;        // 129
    int* sTq = (int*)(sm + 22657);  // 64
    int* sTk = (int*)(sm + 22721);  // [2][64]
    float2* sET = (float2*)(sm + 22850);  // 21 x {k0, e^(k0+1)} — EVEN offset (8B aligned)

    int tid = threadIdx.x;
    int hofQ = 512 + head * 64, hofK = 768 + head * 64, hofV = 256 + head * 64;

    auto pfKV = [&](int kt, int buf) {
        int k0 = kt * 64;
        if (tid < 64) sTk[buf * 64 + tid] = ts[b * Nn + k0 + tid];
        float* dK = sKb + buf * 4608;
        float* dV = sVb + buf * 4352;
#pragma unroll
        for (int p = 0; p < 4; p++) {
            int l = tid + p * 256;
            int row = l >> 4, f4 = (l & 15) << 2;
            int c = row & 7;
            int prow = (row & ~7) | ((c & 1) ? 4 + (c >> 1) : (c >> 1));
            const float* src = &h[(size_t)(base + k0 + row) * 1024];
            cpa16(&dK[row * 72 + f4], src + hofK + f4);
            cpa16(&dV[prow * 68 + f4], src + hofV + f4);
        }
    };

    if (tid < 129) sW[tid] = ts_w[tid];
    if (tid < 64) sTq[tid] = ts[b * Nn + q0 + tid];
    if (tid >= 160 && tid < 181) {  // bucket table init
        int e = tid - 160;
        int k0 = (int)((float)e * 0.69314718f);
        sET[e] = make_float2((float)k0, expf((float)(k0 + 1)));
    }
#pragma unroll
    for (int p = 0; p < 4; p++) {
        int l = tid + p * 256;
        int row = l >> 4, f4 = (l & 15) << 2;
        cpa16(&sQS[row * 72 + f4], &h[(size_t)(base + q0 + row) * 1024 + hofQ + f4]);
    }
    pfKV(kt0, 0);
    cpa_commit();

    int lane = tid & 31, wid = tid >> 5;
    int g = lane >> 2, t = lane & 3;
    int m0 = (wid >> 1) * 16, n0 = (wid & 1) * 32;
    int mgrp = wid >> 1;
    float o[4][4] = {};

    cpa_wait0();
    __syncthreads();

    // hoist Q fragments (h's q-section is alpha-permuted: pair (t,t+4) adjacent)
    float qf[8][4];
#pragma unroll
    for (int ks = 0; ks < 8; ks++) {
        float2 f0 = *reinterpret_cast<const float2*>(&sQS[(m0 + g) * 72 + ks * 8 + 2 * t]);
        float2 f1 = *reinterpret_cast<const float2*>(&sQS[(m0 + g + 8) * 72 + ks * 8 + 2 * t]);
        qf[ks][0] = f0.x; qf[ks][1] = f1.x; qf[ks][2] = f0.y; qf[ks][3] = f1.y;
    }
    __syncthreads();  // all Q frag reads done before sQS is reused as S

    for (int ii = 0; ii < nkt; ii++) {
        int kt = kt0 + ii;
        int buf = ii & 1;
        if (ii + 1 < nkt) { pfKV(kt + 1, buf ^ 1); cpa_commit(); }

        float* sK = sKb + buf * 4608;
        float* sV = sVb + buf * 4352;
        int* sTkb = sTk + buf * 64;
        int k0 = kt * 64;

        // ---- S = Q K^T ----
        float s4[4][4] = {};
#pragma unroll
        for (int ks = 0; ks < 8; ks++) {
#pragma unroll
            for (int j = 0; j < 4; j++) {
                float2 kb = *reinterpret_cast<const float2*>(
                    &sK[(n0 + 8 * j + g) * 72 + ks * 8 + 2 * t]);
                float bb[2] = {kb.x, kb.y};
                mma8(s4[j], qf[ks], bb);
            }
        }

        // ---- score: bias (exp-bit bucket) + silu (HW tanh) + /N + causal ----
        int tq0 = sTq[m0 + g], tq1 = sTq[m0 + g + 8];
        int qg0 = q0 + m0 + g, qg1 = qg0 + 8;
#pragma unroll
        for (int j = 0; j < 4; j++) {
            int col = n0 + 8 * j + 2 * t;
            int tk0 = sTkb[col], tk1 = sTkb[col + 1];
            int kg0 = k0 + col, kg1 = kg0 + 1;
            float r[4];
            int tqs[4] = {tq0, tq0, tq1, tq1};
            int tks[4] = {tk0, tk1, tk0, tk1};
            int qgs[4] = {qg0, qg0, qg1, qg1};
            int kgs[4] = {kg0, kg1, kg0, kg1};
#pragma unroll
            for (int e = 0; e < 4; e++) {
                float w = fabsf((float)(tqs[e] - tks[e])) + 1.0f;
                int ex = (int)(__float_as_uint(w) >> 23) - 127;
                float2 et = sET[ex];
                int bk = (int)et.x + (w >= et.y ? 1 : 0);
                float z = s4[j][e] + sW[bk];
                float sig = fmaf(0.5f, tanh_hw(0.5f * z), 0.5f);
                float zz = z * sig * INV_N;
                r[e] = (kgs[e] <= qgs[e]) ? zz : 0.f;
            }
            *reinterpret_cast<float2*>(&sQS[(m0 + g) * 72 + col]) =
                make_float2(tf32r(r[0]), tf32r(r[1]));
            *reinterpret_cast<float2*>(&sQS[(m0 + g + 8) * 72 + col]) =
                make_float2(tf32r(r[2]), tf32r(r[3]));
        }
        // S rows are private to this m-group; sync only its 2 warps
        asm volatile("bar.sync %0, 64;" :: "r"(1 + mgrp));

        // ---- O += S V ---- (V rows permuted so (t,t+4) S-pairs are adjacent)
#pragma unroll
        for (int ks = 0; ks < 8; ks++) {
            float2 s0 = *reinterpret_cast<const float2*>(&sQS[(m0 + g) * 72 + ks * 8 + 2 * t]);
            float2 s1 = *reinterpret_cast<const float2*>(&sQS[(m0 + g + 8) * 72 + ks * 8 + 2 * t]);
            float a[4] = {s0.x, s1.x, s0.y, s1.y};
#pragma unroll
            for (int j = 0; j < 4; j++) {
                float bb[2];
                bb[0] = sV[(ks * 8 + t) * 68 + n0 + 8 * j + g];
                bb[1] = sV[(ks * 8 + t + 4) * 68 + n0 + 8 * j + g];
                mma8(o[j], a, bb);
            }
        }

        if (ii + 1 < nkt) { cpa_wait0(); __syncthreads(); }
    }

    // accumulate into g_attn
#pragma unroll
    for (int j = 0; j < 4; j++) {
        int col = head * 64 + n0 + 8 * j + 2 * t;
        float* p0 = &attn[(size_t)(base + q0 + m0 + g) * 256 + col];
        float* p1 = &attn[(size_t)(base + q0 + m0 + g + 8) * 256 + col];
        atomicAdd(p0, o[j][0]);
        atomicAdd(p0 + 1, o[j][1]);
        atomicAdd(p1, o[j][2]);
        atomicAdd(p1 + 1, o[j][3]);
    }
}

// ---------------------------------------------------------------------------
// o_in = tf32r(u * ln(attn)), warp-per-row
// ---------------------------------------------------------------------------
__global__ __launch_bounds__(256) void ln_u_kernel(const float* __restrict__ attn,
                                                   const float* __restrict__ h,
                                                   float* __restrict__ oin) {
    int row = blockIdx.x * 8 + (threadIdx.x >> 5);
    int lane = threadIdx.x & 31;
    const float* r = attn + (size_t)row * 256;
    float4 v[2];
    float s = 0.f, q = 0.f;
#pragma unroll
    for (int i = 0; i < 2; i++) {
        v[i] = *reinterpret_cast<const float4*>(&r[lane * 4 + i * 128]);
        s += v[i].x + v[i].y + v[i].z + v[i].w;
        q += v[i].x * v[i].x + v[i].y * v[i].y + v[i].z * v[i].z + v[i].w * v[i].w;
    }
#pragma unroll
    for (int o = 16; o > 0; o >>= 1) {
        s += __shfl_xor_sync(0xffffffffu, s, o);
        q += __shfl_xor_sync(0xffffffffu, q, o);
    }
    float m = s * (1.f / 256.f);
    float rstd = rsqrtf(q * (1.f / 256.f) - m * m + 1e-6f);
    float* ov = oin + (size_t)row * 256;
#pragma unroll
    for (int i = 0; i < 2; i++) {
        float4 u4 = *reinterpret_cast<const float4*>(
            &h[(size_t)row * 1024 + lane * 4 + i * 128]);
        float4 w;
        w.x = tf32r(u4.x * (v[i].x - m) * rstd);
        w.y = tf32r(u4.y * (v[i].y - m) * rstd);
        w.z = tf32r(u4.z * (v[i].z - m) * rstd);
        w.w = tf32r(u4.w * (v[i].w - m) * rstd);
        *reinterpret_cast<float4*>(&ov[lane * 4 + i * 128]) = w;
    }
}

// ---------------------------------------------------------------------------
// out = o_in @ o_w^T + o_b + x    tf32 MMA, 128x64 tile
// ---------------------------------------------------------------------------
__global__ __launch_bounds__(256) void gemm_out_kernel(const float* __restrict__ A,
                                                       const float* __restrict__ W,
                                                       const float* __restrict__ bias,
                                                       const float* __restrict__ x,
                                                       float* __restrict__ out) {
    __shared__ float sA[128][36];
    __shared__ float sB[32][65];
    int bm = blockIdx.y * 128, bn = blockIdx.x * 64;
    int tid = threadIdx.x, lane = tid & 31, wid = tid >> 5;
    int g = lane >> 2, t = lane & 3;
    int wm = (wid >> 1) * 32, wn = (wid & 1) * 32;
    float acc[2][4][4] = {};
    for (int k0 = 0; k0 < 256; k0 += 32) {
#pragma unroll
        for (int p = 0; p < 4; p++) {
            int idx = tid + p * 256;
            int row = idx >> 3, f4 = (idx & 7) << 2;
            float4 v = *reinterpret_cast<const float4*>(
                &A[(size_t)(bm + row) * 256 + k0 + f4]);
            *reinterpret_cast<float4*>(&sA[row][f4]) = v;
        }
#pragma unroll
        for (int p = 0; p < 2; p++) {
            int idx = tid + p * 256;
            int nr = idx >> 3, f4 = (idx & 7) << 2;
            float4 v = tf32r4(*reinterpret_cast<const float4*>(
                &W[(size_t)(bn + nr) * 256 + k0 + f4]));
            sB[f4 + 0][nr] = v.x; sB[f4 + 1][nr] = v.y;
            sB[f4 + 2][nr] = v.z; sB[f4 + 3][nr] = v.w;
        }
        __syncthreads();
#pragma unroll
        for (int kk = 0; kk < 32; kk += 8) {
            float a[2][4], bb[4][2];
#pragma unroll
            for (int i = 0; i < 2; i++) {
                int r = wm + 16 * i + g;
                a[i][0] = sA[r][kk + t];
                a[i][1] = sA[r + 8][kk + t];
                a[i][2] = sA[r][kk + t + 4];
                a[i][3] = sA[r + 8][kk + t + 4];
            }
#pragma unroll
            for (int j = 0; j < 4; j++) {
                bb[j][0] = sB[kk + t][wn + 8 * j + g];
                bb[j][1] = sB[kk + t + 4][wn + 8 * j + g];
            }
#pragma unroll
            for (int i = 0; i < 2; i++)
#pragma unroll
                for (int j = 0; j < 4; j++) mma8(acc[i][j], a[i], bb[j]);
        }
        __syncthreads();
    }
#pragma unroll
    for (int i = 0; i < 2; i++) {
        int r = bm + wm + 16 * i + g;
#pragma unroll
        for (int j = 0; j < 4; j++) {
            int c = bn + wn + 8 * j + 2 * t;
            float2 b2 = *reinterpret_cast<const float2*>(&bias[c]);
            float2 x0 = *reinterpret_cast<const float2*>(&x[(size_t)r * Dm + c]);
            float2 x1 = *reinterpret_cast<const float2*>(&x[(size_t)(r + 8) * Dm + c]);
            float* s = acc[i][j];
            *reinterpret_cast<float2*>(&out[(size_t)r * Dm + c]) =
                make_float2(s[0] + b2.x + x0.x, s[1] + b2.y + x0.y);
            *reinterpret_cast<float2*>(&out[(size_t)(r + 8) * Dm + c]) =
                make_float2(s[2] + b2.x + x1.x, s[3] + b2.y + x1.y);
        }
    }
}

// ---------------------------------------------------------------------------
extern "C" void kernel_launch(void* const* d_in, const int* in_sizes, int n_in,
                              void* d_out, int out_size) {
    const float* x    = (const float*)d_in[0];
    const float* uvqk = (const float*)d_in[1];
    const float* o_w  = (const float*)d_in[2];
    const float* o_b  = (const float*)d_in[3];
    const float* ts_w = (const float*)d_in[4];
    const int*   ts   = (const int*)d_in[5];
    float* out = (float*)d_out;

    float *xn, *uvqkr, *h, *attn, *oin;
    cudaGetSymbolAddress((void**)&xn,    g_xn);
    cudaGetSymbolAddress((void**)&uvqkr, g_uvqkr);
    cudaGetSymbolAddress((void**)&h,     g_h);
    cudaGetSymbolAddress((void**)&attn,  g_attn);
    cudaGetSymbolAddress((void**)&oin,   g_oin);

    cudaFuncSetAttribute(attn_kernel, cudaFuncAttributeMaxDynamicSharedMemorySize,
                         ATTN_SMEM);
    cudaFuncSetAttribute(gemm_silu_kernel, cudaFuncAttributeMaxDynamicSharedMemorySize,
                         G1_SMEM);

    cudaMemsetAsync(attn, 0, (size_t)T_ * 256 * sizeof(float));
    ln_x_kernel<<<800, 256>>>(x, xn);
    cvt_tf32_kernel<<<512, 256>>>((const float4*)uvqk, (float4*)uvqkr);
    gemm_silu_kernel<<<dim3(16, 50), 256, G1_SMEM>>>(xn, uvqkr, h);
    attn_kernel<<<dim3(216, 4), 256, ATTN_SMEM>>>(h, ts, ts_w, attn);
    ln_u_kernel<<<800, 256>>>(attn, h, oin);
    gemm_out_kernel<<<dim3(8, 50), 256>>>(oin, o_w, o_b, x, out);
}

// round 12
// speedup vs baseline: 1.0758x; 1.0758x over previous
#include <cuda_runtime.h>
#include <math.h>
#include <stdint.h>

#define T_   6400
#define Dm   512
#define Nn   2048
#define NBUCK 128
#define INV_N (1.0f / 2048.0f)

// offsets = [0, 2048, 3584, 4608, 6400]; lengths all multiples of 64.
__constant__ int c_off[5] = {0, 2048, 3584, 4608, 6400};

__device__ float g_xn[(size_t)T_ * Dm];
__device__ float g_uvqkr[(size_t)Dm * 1024];
__device__ float g_h[(size_t)T_ * 1024];
__device__ float g_vT[(size_t)256 * T_];   // V transposed: [feature][token]
__device__ float g_attn[(size_t)T_ * 256];
__device__ float g_oin[(size_t)T_ * 256];

// ---- tf32 / mma / cp.async helpers ----------------------------------------
__device__ __forceinline__ float tf32r(float x) {
    float y; asm("cvt.rna.tf32.f32 %0, %1;" : "=f"(y) : "f"(x)); return y;
}
__device__ __forceinline__ float4 tf32r4(float4 v) {
    v.x = tf32r(v.x); v.y = tf32r(v.y); v.z = tf32r(v.z); v.w = tf32r(v.w);
    return v;
}
__device__ __forceinline__ float tanh_hw(float x) {
    float y; asm("tanh.approx.f32 %0, %1;" : "=f"(y) : "f"(x)); return y;
}
__device__ __forceinline__ void mma8(float* c, const float* a, const float* b) {
    asm volatile(
        "mma.sync.aligned.m16n8k8.row.col.f32.tf32.tf32.f32 "
        "{%0,%1,%2,%3},{%4,%5,%6,%7},{%8,%9},{%0,%1,%2,%3};"
        : "+f"(c[0]), "+f"(c[1]), "+f"(c[2]), "+f"(c[3])
        : "r"(__float_as_uint(a[0])), "r"(__float_as_uint(a[1])),
          "r"(__float_as_uint(a[2])), "r"(__float_as_uint(a[3])),
          "r"(__float_as_uint(b[0])), "r"(__float_as_uint(b[1])));
}
__device__ __forceinline__ void cpa16(void* dst, const void* src) {
    uint32_t d = (uint32_t)__cvta_generic_to_shared(dst);
    asm volatile("cp.async.cg.shared.global [%0], [%1], 16;" :: "r"(d), "l"(src));
}
__device__ __forceinline__ void cpa_commit() { asm volatile("cp.async.commit_group;"); }
__device__ __forceinline__ void cpa_wait0()  { asm volatile("cp.async.wait_group 0;"); }

// ---------------------------------------------------------------------------
// tf32 pre-round of uvqk
// ---------------------------------------------------------------------------
__global__ __launch_bounds__(256) void cvt_tf32_kernel(const float4* __restrict__ in,
                                                       float4* __restrict__ out) {
    int i = blockIdx.x * 256 + threadIdx.x;
    out[i] = tf32r4(in[i]);
}

// ---------------------------------------------------------------------------
// LayerNorm over D=512, warp-per-row, tf32-rounded output
// ---------------------------------------------------------------------------
__global__ __launch_bounds__(256) void ln_x_kernel(const float* __restrict__ x,
                                                   float* __restrict__ xn) {
    int row = blockIdx.x * 8 + (threadIdx.x >> 5);
    int lane = threadIdx.x & 31;
    const float* r = x + (size_t)row * Dm;
    float4 v[4];
    float s = 0.f, q = 0.f;
#pragma unroll
    for (int i = 0; i < 4; i++) {
        v[i] = *reinterpret_cast<const float4*>(&r[lane * 4 + i * 128]);
        s += v[i].x + v[i].y + v[i].z + v[i].w;
        q += v[i].x * v[i].x + v[i].y * v[i].y + v[i].z * v[i].z + v[i].w * v[i].w;
    }
#pragma unroll
    for (int o = 16; o > 0; o >>= 1) {
        s += __shfl_xor_sync(0xffffffffu, s, o);
        q += __shfl_xor_sync(0xffffffffu, q, o);
    }
    float m = s * (1.f / Dm);
    float rstd = rsqrtf(q * (1.f / Dm) - m * m + 1e-6f);
    float* ov = xn + (size_t)row * Dm;
#pragma unroll
    for (int i = 0; i < 4; i++) {
        float4 w;
        w.x = tf32r((v[i].x - m) * rstd); w.y = tf32r((v[i].y - m) * rstd);
        w.z = tf32r((v[i].z - m) * rstd); w.w = tf32r((v[i].w - m) * rstd);
        *reinterpret_cast<float4*>(&ov[lane * 4 + i * 128]) = w;
    }
}

// ---------------------------------------------------------------------------
// h = silu(xn @ uvqkr)  tf32 MMA, 128x64 tile, BK=32, cp.async double buffer.
// u section (cols<256): natural -> h.  v section (256..512): TRANSPOSED -> g_vT.
// q/k sections (cols>=512): per-8-col interleave permutation -> h.
// ---------------------------------------------------------------------------
#define G1_SMEM ((2 * (128 * 36 + 32 * 72)) * 4)

__global__ __launch_bounds__(256) void gemm_silu_kernel(const float* __restrict__ A,
                                                        const float* __restrict__ Bm,
                                                        float* __restrict__ C,
                                                        float* __restrict__ vT) {
    extern __shared__ float sm[];
    float* sA = sm;            // [2][128][36]
    float* sB = sm + 9216;     // [2][32][72]
    int bm = blockIdx.y * 128, bn = blockIdx.x * 64;
    int tid = threadIdx.x, lane = tid & 31, wid = tid >> 5;
    int g = lane >> 2, t = lane & 3;
    int wm = (wid >> 1) * 32, wn = (wid & 1) * 32;

    auto pf = [&](int k0, int buf) {
        float* dA = sA + buf * 4608;
        float* dB = sB + buf * 2304;
#pragma unroll
        for (int p = 0; p < 4; p++) {
            int idx = tid + p * 256;
            int row = idx >> 3, f4 = (idx & 7) << 2;
            cpa16(&dA[row * 36 + f4], &A[(size_t)(bm + row) * Dm + k0 + f4]);
        }
#pragma unroll
        for (int p = 0; p < 2; p++) {
            int idx = tid + p * 256;
            int row = idx >> 4, f4 = (idx & 15) << 2;
            cpa16(&dB[row * 72 + f4], &Bm[(size_t)(k0 + row) * 1024 + bn + f4]);
        }
        cpa_commit();
    };

    float acc[2][4][4] = {};
    pf(0, 0);
    for (int it = 0; it < 16; it++) {
        cpa_wait0();
        __syncthreads();
        if (it + 1 < 16) pf((it + 1) * 32, (it + 1) & 1);
        float* cA = sA + (it & 1) * 4608;
        float* cB = sB + (it & 1) * 2304;
#pragma unroll
        for (int kk = 0; kk < 32; kk += 8) {
            float a[2][4], bb[4][2];
#pragma unroll
            for (int i = 0; i < 2; i++) {
                int r = wm + 16 * i + g;
                a[i][0] = cA[r * 36 + kk + t];
                a[i][1] = cA[(r + 8) * 36 + kk + t];
                a[i][2] = cA[r * 36 + kk + t + 4];
                a[i][3] = cA[(r + 8) * 36 + kk + t + 4];
            }
#pragma unroll
            for (int j = 0; j < 4; j++) {
                bb[j][0] = cB[(kk + t) * 72 + wn + 8 * j + g];
                bb[j][1] = cB[(kk + t + 4) * 72 + wn + 8 * j + g];
            }
#pragma unroll
            for (int i = 0; i < 2; i++)
#pragma unroll
                for (int j = 0; j < 4; j++) mma8(acc[i][j], a[i], bb[j]);
        }
        __syncthreads();
    }
    int sec = bn >> 8;                    // 0: u, 1: v, >=2: q/k
    int p0 = (t < 2) ? 4 * t : 4 * t - 7; // alpha perm for q/k
#pragma unroll
    for (int i = 0; i < 2; i++) {
        int r = bm + wm + 16 * i + g;
#pragma unroll
        for (int j = 0; j < 4; j++) {
            float* s = acc[i][j];
            float e0 = tf32r(__fdividef(s[0], 1.f + __expf(-s[0])));
            float e1 = tf32r(__fdividef(s[1], 1.f + __expf(-s[1])));
            float e2 = tf32r(__fdividef(s[2], 1.f + __expf(-s[2])));
            float e3 = tf32r(__fdividef(s[3], 1.f + __expf(-s[3])));
            if (sec == 0) {
                int c = bn + wn + 8 * j + 2 * t;
                *reinterpret_cast<float2*>(&C[(size_t)r * 1024 + c]) = make_float2(e0, e1);
                *reinterpret_cast<float2*>(&C[(size_t)(r + 8) * 1024 + c]) = make_float2(e2, e3);
            } else if (sec == 1) {
                int f = (bn - 256) + wn + 8 * j + 2 * t;   // 0..255
                vT[(size_t)f * T_ + r] = e0;
                vT[(size_t)(f + 1) * T_ + r] = e1;
                vT[(size_t)f * T_ + r + 8] = e2;
                vT[(size_t)(f + 1) * T_ + r + 8] = e3;
            } else {
                int cb = bn + wn + 8 * j;
                C[(size_t)r * 1024 + cb + p0] = e0;
                C[(size_t)r * 1024 + cb + p0 + 2] = e1;
                C[(size_t)(r + 8) * 1024 + cb + p0] = e2;
                C[(size_t)(r + 8) * 1024 + cb + p0 + 2] = e3;
            }
        }
    }
}

// ---------------------------------------------------------------------------
// Split-K jagged causal attention. V read from g_vT (transposed) so SV
// B-fragments are single LDS.64. Diagonal-only causal masking.
// ---------------------------------------------------------------------------
#define ATTN_SMEM (23404 * 4)

__global__ __launch_bounds__(256) void attn_kernel(const float* __restrict__ h,
                                                   const float* __restrict__ vT,
                                                   const int* __restrict__ ts,
                                                   const float* __restrict__ ts_w,
                                                   float* __restrict__ attn) {
    // decode unit -> (b, tile, chunk); chunks(t) = (t>>3)+1, tiles descending
    int u = blockIdx.x;
    int b;
    if (u < 80) { b = 0; }
    else if (u < 128) { b = 1; u -= 80; }
    else if (u < 152) { b = 2; u -= 128; }
    else { b = 3; u -= 152; }
    int base = c_off[b];
    int Tb = (c_off[b + 1] - base) >> 6;
    int tile = 0, chunk = 0;
    for (int tt = Tb - 1; tt >= 0; --tt) {
        int c = (tt >> 3) + 1;
        if (u < c) { tile = tt; chunk = u; break; }
        u -= c;
    }
    int head = blockIdx.y;
    int q0 = tile * 64;
    int kt0 = chunk * 8;
    int nkt = min(kt0 + 8, tile + 1) - kt0;

    extern __shared__ float sm[];
    float* sQS = sm;                // [64][72]: Q during init, then S
    float* sKb = sm + 4608;         // [2][64][72]
    float* sVT = sm + 13824;        // [2][64][72]  V^T tiles: [d][key]
    float* sW  = sm + 23040;        // 129
    int* sTq = (int*)(sm + 23169);  // 64
    int* sTk = (int*)(sm + 23233);  // [2][64]
    float2* sET = (float2*)(sm + 23362);  // 21 x {k0, e^(k0+1)}, 8B aligned

    int tid = threadIdx.x;
    int hofQ = 512 + head * 64, hofK = 768 + head * 64;
    const float* vTh = vT + (size_t)head * 64 * T_;

    auto pfKV = [&](int kt, int buf) {
        int k0 = kt * 64;
        if (tid < 64) sTk[buf * 64 + tid] = ts[b * Nn + k0 + tid];
        float* dK = sKb + buf * 4608;
        float* dV = sVT + buf * 4608;
#pragma unroll
        for (int p = 0; p < 4; p++) {
            int l = tid + p * 256;
            int row = l >> 4, f4 = (l & 15) << 2;
            cpa16(&dK[row * 72 + f4],
                  &h[(size_t)(base + k0 + row) * 1024 + hofK + f4]);
            cpa16(&dV[row * 72 + f4],
                  &vTh[(size_t)row * T_ + base + k0 + f4]);
        }
    };

    if (tid < 129) sW[tid] = ts_w[tid];
    if (tid < 64) sTq[tid] = ts[b * Nn + q0 + tid];
    if (tid >= 160 && tid < 181) {  // bucket table init
        int e = tid - 160;
        int k0 = (int)((float)e * 0.69314718f);
        sET[e] = make_float2((float)k0, expf((float)(k0 + 1)));
    }
#pragma unroll
    for (int p = 0; p < 4; p++) {
        int l = tid + p * 256;
        int row = l >> 4, f4 = (l & 15) << 2;
        cpa16(&sQS[row * 72 + f4], &h[(size_t)(base + q0 + row) * 1024 + hofQ + f4]);
    }
    pfKV(kt0, 0);
    cpa_commit();

    int lane = tid & 31, wid = tid >> 5;
    int g = lane >> 2, t = lane & 3;
    int m0 = (wid >> 1) * 16, n0 = (wid & 1) * 32;
    int mgrp = wid >> 1;
    float o[4][4] = {};

    cpa_wait0();
    __syncthreads();

    // hoist Q fragments (h's q-section is alpha-permuted: pair (t,t+4) adjacent)
    float qf[8][4];
#pragma unroll
    for (int ks = 0; ks < 8; ks++) {
        float2 f0 = *reinterpret_cast<const float2*>(&sQS[(m0 + g) * 72 + ks * 8 + 2 * t]);
        float2 f1 = *reinterpret_cast<const float2*>(&sQS[(m0 + g + 8) * 72 + ks * 8 + 2 * t]);
        qf[ks][0] = f0.x; qf[ks][1] = f1.x; qf[ks][2] = f0.y; qf[ks][3] = f1.y;
    }
    __syncthreads();  // all Q frag reads done before sQS is reused as S

    for (int ii = 0; ii < nkt; ii++) {
        int kt = kt0 + ii;
        int buf = ii & 1;
        if (ii + 1 < nkt) { pfKV(kt + 1, buf ^ 1); cpa_commit(); }

        float* sK = sKb + buf * 4608;
        float* sV = sVT + buf * 4608;
        int* sTkb = sTk + buf * 64;

        // ---- S = Q K^T ----
        float s4[4][4] = {};
#pragma unroll
        for (int ks = 0; ks < 8; ks++) {
#pragma unroll
            for (int j = 0; j < 4; j++) {
                float2 kb = *reinterpret_cast<const float2*>(
                    &sK[(n0 + 8 * j + g) * 72 + ks * 8 + 2 * t]);
                float bb[2] = {kb.x, kb.y};
                mma8(s4[j], qf[ks], bb);
            }
        }

        // ---- score: bias (exp-bit bucket) + silu (HW tanh) + /N; mask on diag ----
        int tq0 = sTq[m0 + g], tq1 = sTq[m0 + g + 8];
        bool diag = (kt == tile);
#pragma unroll
        for (int j = 0; j < 4; j++) {
            int col = n0 + 8 * j + 2 * t;
            int tk0 = sTkb[col], tk1 = sTkb[col + 1];
            float r[4];
            int tqs[4] = {tq0, tq0, tq1, tq1};
            int tks[4] = {tk0, tk1, tk0, tk1};
#pragma unroll
            for (int e = 0; e < 4; e++) {
                float w = fabsf((float)(tqs[e] - tks[e])) + 1.0f;
                int ex = (int)(__float_as_uint(w) >> 23) - 127;
                float2 et = sET[ex];
                int bk = (int)et.x + (w >= et.y ? 1 : 0);
                float z = s4[j][e] + sW[bk];
                float sig = fmaf(0.5f, tanh_hw(0.5f * z), 0.5f);
                r[e] = z * sig * INV_N;
            }
            if (diag) {
                int qg0 = m0 + g, qg1 = qg0 + 8;     // local indices suffice on diag
                if (col > qg0) r[0] = 0.f;
                if (col + 1 > qg0) r[1] = 0.f;
                if (col > qg1) r[2] = 0.f;
                if (col + 1 > qg1) r[3] = 0.f;
            }
            *reinterpret_cast<float2*>(&sQS[(m0 + g) * 72 + col]) =
                make_float2(tf32r(r[0]), tf32r(r[1]));
            *reinterpret_cast<float2*>(&sQS[(m0 + g + 8) * 72 + col]) =
                make_float2(tf32r(r[2]), tf32r(r[3]));
        }
        // S rows are private to this m-group; sync only its 2 warps
        asm volatile("bar.sync %0, 64;" :: "r"(1 + mgrp));

        // ---- O += S V ----  (V^T: keys 2t,2t+1 adjacent -> LDS.64 B-frags)
#pragma unroll
        for (int ks = 0; ks < 8; ks++) {
            float2 s0 = *reinterpret_cast<const float2*>(&sQS[(m0 + g) * 72 + ks * 8 + 2 * t]);
            float2 s1 = *reinterpret_cast<const float2*>(&sQS[(m0 + g + 8) * 72 + ks * 8 + 2 * t]);
            float a[4] = {s0.x, s1.x, s0.y, s1.y};
#pragma unroll
            for (int j = 0; j < 4; j++) {
                float2 vb = *reinterpret_cast<const float2*>(
                    &sV[(n0 + 8 * j + g) * 72 + ks * 8 + 2 * t]);
                float bb[2] = {vb.x, vb.y};
                mma8(o[j], a, bb);
            }
        }

        if (ii + 1 < nkt) { cpa_wait0(); __syncthreads(); }
    }

    // accumulate into g_attn
#pragma unroll
    for (int j = 0; j < 4; j++) {
        int col = head * 64 + n0 + 8 * j + 2 * t;
        float* p0 = &attn[(size_t)(base + q0 + m0 + g) * 256 + col];
        float* p1 = &attn[(size_t)(base + q0 + m0 + g + 8) * 256 + col];
        atomicAdd(p0, o[j][0]);
        atomicAdd(p0 + 1, o[j][1]);
        atomicAdd(p1, o[j][2]);
        atomicAdd(p1 + 1, o[j][3]);
    }
}

// ---------------------------------------------------------------------------
// o_in = tf32r(u * ln(attn)), warp-per-row
// ---------------------------------------------------------------------------
__global__ __launch_bounds__(256) void ln_u_kernel(const float* __restrict__ attn,
                                                   const float* __restrict__ h,
                                                   float* __restrict__ oin) {
    int row = blockIdx.x * 8 + (threadIdx.x >> 5);
    int lane = threadIdx.x & 31;
    const float* r = attn + (size_t)row * 256;
    float4 v[2];
    float s = 0.f, q = 0.f;
#pragma unroll
    for (int i = 0; i < 2; i++) {
        v[i] = *reinterpret_cast<const float4*>(&r[lane * 4 + i * 128]);
        s += v[i].x + v[i].y + v[i].z + v[i].w;
        q += v[i].x * v[i].x + v[i].y * v[i].y + v[i].z * v[i].z + v[i].w * v[i].w;
    }
#pragma unroll
    for (int o = 16; o > 0; o >>= 1) {
        s += __shfl_xor_sync(0xffffffffu, s, o);
        q += __shfl_xor_sync(0xffffffffu, q, o);
    }
    float m = s * (1.f / 256.f);
    float rstd = rsqrtf(q * (1.f / 256.f) - m * m + 1e-6f);
    float* ov = oin + (size_t)row * 256;
#pragma unroll
    for (int i = 0; i < 2; i++) {
        float4 u4 = *reinterpret_cast<const float4*>(
            &h[(size_t)row * 1024 + lane * 4 + i * 128]);
        float4 w;
        w.x = tf32r(u4.x * (v[i].x - m) * rstd);
        w.y = tf32r(u4.y * (v[i].y - m) * rstd);
        w.z = tf32r(u4.z * (v[i].z - m) * rstd);
        w.w = tf32r(u4.w * (v[i].w - m) * rstd);
        *reinterpret_cast<float4*>(&ov[lane * 4 + i * 128]) = w;
    }
}

// ---------------------------------------------------------------------------
// out = o_in @ o_w^T + o_b + x    tf32 MMA, 128x64 tile
// ---------------------------------------------------------------------------
__global__ __launch_bounds__(256) void gemm_out_kernel(const float* __restrict__ A,
                                                       const float* __restrict__ W,
                                                       const float* __restrict__ bias,
                                                       const float* __restrict__ x,
                                                       float* __restrict__ out) {
    __shared__ float sA[128][36];
    __shared__ float sB[32][65];
    int bm = blockIdx.y * 128, bn = blockIdx.x * 64;
    int tid = threadIdx.x, lane = tid & 31, wid = tid >> 5;
    int g = lane >> 2, t = lane & 3;
    int wm = (wid >> 1) * 32, wn = (wid & 1) * 32;
    float acc[2][4][4] = {};
    for (int k0 = 0; k0 < 256; k0 += 32) {
#pragma unroll
        for (int p = 0; p < 4; p++) {
            int idx = tid + p * 256;
            int row = idx >> 3, f4 = (idx & 7) << 2;
            float4 v = *reinterpret_cast<const float4*>(
                &A[(size_t)(bm + row) * 256 + k0 + f4]);
            *reinterpret_cast<float4*>(&sA[row][f4]) = v;
        }
#pragma unroll
        for (int p = 0; p < 2; p++) {
            int idx = tid + p * 256;
            int nr = idx >> 3, f4 = (idx & 7) << 2;
            float4 v = tf32r4(*reinterpret_cast<const float4*>(
                &W[(size_t)(bn + nr) * 256 + k0 + f4]));
            sB[f4 + 0][nr] = v.x; sB[f4 + 1][nr] = v.y;
            sB[f4 + 2][nr] = v.z; sB[f4 + 3][nr] = v.w;
        }
        __syncthreads();
#pragma unroll
        for (int kk = 0; kk < 32; kk += 8) {
            float a[2][4], bb[4][2];
#pragma unroll
            for (int i = 0; i < 2; i++) {
                int r = wm + 16 * i + g;
                a[i][0] = sA[r][kk + t];
                a[i][1] = sA[r + 8][kk + t];
                a[i][2] = sA[r][kk + t + 4];
                a[i][3] = sA[r + 8][kk + t + 4];
            }
#pragma unroll
            for (int j = 0; j < 4; j++) {
                bb[j][0] = sB[kk + t][wn + 8 * j + g];
                bb[j][1] = sB[kk + t + 4][wn + 8 * j + g];
            }
#pragma unroll
            for (int i = 0; i < 2; i++)
#pragma unroll
                for (int j = 0; j < 4; j++) mma8(acc[i][j], a[i], bb[j]);
        }
        __syncthreads();
    }
#pragma unroll
    for (int i = 0; i < 2; i++) {
        int r = bm + wm + 16 * i + g;
#pragma unroll
        for (int j = 0; j < 4; j++) {
            int c = bn + wn + 8 * j + 2 * t;
            float2 b2 = *reinterpret_cast<const float2*>(&bias[c]);
            float2 x0 = *reinterpret_cast<const float2*>(&x[(size_t)r * Dm + c]);
            float2 x1 = *reinterpret_cast<const float2*>(&x[(size_t)(r + 8) * Dm + c]);
            float* s = acc[i][j];
            *reinterpret_cast<float2*>(&out[(size_t)r * Dm + c]) =
                make_float2(s[0] + b2.x + x0.x, s[1] + b2.y + x0.y);
            *reinterpret_cast<float2*>(&out[(size_t)(r + 8) * Dm + c]) =
                make_float2(s[2] + b2.x + x1.x, s[3] + b2.y + x1.y);
        }
    }
}

// ---------------------------------------------------------------------------
extern "C" void kernel_launch(void* const* d_in, const int* in_sizes, int n_in,
                              void* d_out, int out_size) {
    const float* x    = (const float*)d_in[0];
    const float* uvqk = (const float*)d_in[1];
    const float* o_w  = (const float*)d_in[2];
    const float* o_b  = (const float*)d_in[3];
    const float* ts_w = (const float*)d_in[4];
    const int*   ts   = (const int*)d_in[5];
    float* out = (float*)d_out;

    float *xn, *uvqkr, *h, *vT, *attn, *oin;
    cudaGetSymbolAddress((void**)&xn,    g_xn);
    cudaGetSymbolAddress((void**)&uvqkr, g_uvqkr);
    cudaGetSymbolAddress((void**)&h,     g_h);
    cudaGetSymbolAddress((void**)&vT,    g_vT);
    cudaGetSymbolAddress((void**)&attn,  g_attn);
    cudaGetSymbolAddress((void**)&oin,   g_oin);

    cudaFuncSetAttribute(attn_kernel, cudaFuncAttributeMaxDynamicSharedMemorySize,
                         ATTN_SMEM);
    cudaFuncSetAttribute(gemm_silu_kernel, cudaFuncAttributeMaxDynamicSharedMemorySize,
                         G1_SMEM);

    cudaMemsetAsync(attn, 0, (size_t)T_ * 256 * sizeof(float));
    ln_x_kernel<<<800, 256>>>(x, xn);
    cvt_tf32_kernel<<<512, 256>>>((const float4*)uvqk, (float4*)uvqkr);
    gemm_silu_kernel<<<dim3(16, 50), 256, G1_SMEM>>>(xn, uvqkr, h, vT);
    attn_kernel<<<dim3(216, 4), 256, ATTN_SMEM>>>(h, vT, ts, ts_w, attn);
    ln_u_kernel<<<800, 256>>>(attn, h, oin);
    gemm_out_kernel<<<dim3(8, 50), 256>>>(oin, o_w, o_b, x, out);
}